// round 14
// baseline (speedup 1.0000x reference)
#include <cuda_runtime.h>
#include <cuda_fp16.h>
#include <math.h>
#include <stdint.h>

// ---------------------------------------------------------------------------
// Problem: u (8,4096,1024) f32. Outputs: y (8,4096,1024), gamma, final.
// gamma5 emits u in fp16 + 5 per-row partial dots (register-resident vectors);
// combine kernel forms gamma/final; fused GEMM computes
//   C1[m] = u[m]   @ WB ^T (cols bj..bj+63)   (warps 0-3)
//   C2[m] = u[m+1] @ WBf^T (cols bj..bj+63)   (warps 4-7, +1 row shift)
// and writes y = g*(xf+xb)+(1-g)*u directly. (GEMM identical to R13.)
// ---------------------------------------------------------------------------
#define BB 8
#define TT 4096
#define DD 1024
#define ROWS (BB * TT)              // 32768  (M)
#define KK   DD                     // 1024   (K)
#define Y_ELEMS   (ROWS * DD)
#define G_ELEMS   (ROWS)

// GEMM tiling
#define BM 128
#define XN 64                        // V-columns per CTA (each of C1, C2)
#define BK 64
#define STAGES 3
#define NCHUNK (KK / BK)             // 16
#define OFF_A 0                      // 129 rows x 128B
#define OFF_B 16640
#define STAGE_BYTES 33024            // A(16640) + B(16384)
#define SMEM_DYN (STAGES * STAGE_BYTES)   // 99072
#define CS_STRIDE 68                 // fp32 staging stride (bank-friendly)

// Device-global scratch (no cudaMalloc anywhere)
__device__ __half g_Af[(size_t)ROWS * KK];       // 64 MiB  (u in fp16)
__device__ __half g_Bf[(size_t)2 * DD * KK];     // 4 MiB: rows 0..1023 WB, 1024.. WBf
__device__ float  g_vecs[4 * DD];                // a1 | a2 | cB | cBf
__device__ float  g_part[16][4][DD];             // precompute partials
__device__ float  g_p5[8][5][ROWS];              // per-slice row dots (5.2 MB)
__device__ float  g_bnd[BB][2];                  // u[b,0]·w1, u[b,T-1]·w2
__device__ float  g_gamma[ROWS];

// ---------------------------------------------------------------------------
// PTX helpers (sm_80-class only: cp.async, ldmatrix, mma.sync)
// ---------------------------------------------------------------------------
__device__ __forceinline__ uint32_t smem_u32(const void* p) {
    uint32_t a;
    asm("{ .reg .u64 t; cvta.to.shared.u64 t, %1; cvt.u32.u64 %0, t; }"
        : "=r"(a) : "l"(p));
    return a;
}
__device__ __forceinline__ void cpasync16(uint32_t dst, const void* src) {
    asm volatile("cp.async.cg.shared.global [%0], [%1], 16;" :: "r"(dst), "l"(src));
}
#define CP_COMMIT() asm volatile("cp.async.commit_group;" ::: "memory")
#define CP_WAIT_1() asm volatile("cp.async.wait_group 1;" ::: "memory")
#define CP_WAIT_0() asm volatile("cp.async.wait_group 0;" ::: "memory")

__device__ __forceinline__ void ldm_x4(uint32_t* r, uint32_t addr) {
    asm volatile("ldmatrix.sync.aligned.m8n8.x4.shared.b16 {%0,%1,%2,%3}, [%4];"
                 : "=r"(r[0]), "=r"(r[1]), "=r"(r[2]), "=r"(r[3]) : "r"(addr));
}
__device__ __forceinline__ void mma16816(float* c, const uint32_t* a,
                                         const uint32_t* b) {
    asm volatile("mma.sync.aligned.m16n8k16.row.col.f32.f16.f16.f32 "
                 "{%0,%1,%2,%3}, {%4,%5,%6,%7}, {%8,%9}, {%0,%1,%2,%3};"
                 : "+f"(c[0]), "+f"(c[1]), "+f"(c[2]), "+f"(c[3])
                 : "r"(a[0]), "r"(a[1]), "r"(a[2]), "r"(a[3]),
                   "r"(b[0]), "r"(b[1]));
}
__device__ __forceinline__ float dot4(float4 a, float4 b) {
    return fmaf(a.x, b.x, fmaf(a.y, b.y, fmaf(a.z, b.z, a.w * b.w)));
}

// ---------------------------------------------------------------------------
// K0: [WB;WBf] -> fp16.
// ---------------------------------------------------------------------------
__global__ void convert_w_kernel(const float* __restrict__ WB,
                                 const float* __restrict__ WBf) {
    size_t i = ((size_t)blockIdx.x * 256 + threadIdx.x) * 4;
    const float* src = (i < (size_t)DD * DD) ? (WB + i) : (WBf + i - (size_t)DD * DD);
    float4 x = *(const float4*)src;
    union { __half h[4]; uint2 v; } H;
    H.h[0] = __float2half_rn(x.x);  H.h[1] = __float2half_rn(x.y);
    H.h[2] = __float2half_rn(x.z);  H.h[3] = __float2half_rn(x.w);
    *(uint2*)(g_Bf + i) = H.v;
}

// ---------------------------------------------------------------------------
// K1a/K1b: precompute a1 = w1@WB, a2 = w2@WBf, cB = Wc@WB, cBf = Wc@WBf.
// ---------------------------------------------------------------------------
__global__ void precompute_partial_kernel(const float* __restrict__ WB,
                                          const float* __restrict__ WBf,
                                          const float* __restrict__ w1,
                                          const float* __restrict__ w2,
                                          const float* __restrict__ Wc) {
    int d  = blockIdx.x * 256 + threadIdx.x;   // 0..1023
    int e0 = blockIdx.y * 64;
    float a1 = 0.f, a2 = 0.f, cB = 0.f, cBf = 0.f;
#pragma unroll 8
    for (int e = e0; e < e0 + 64; ++e) {
        float wb = WB[e * DD + d];
        float wf = WBf[e * DD + d];
        a1  += w1[e] * wb;
        cB  += Wc[e] * wb;
        a2  += w2[e] * wf;
        cBf += Wc[e] * wf;
    }
    g_part[blockIdx.y][0][d] = a1;
    g_part[blockIdx.y][1][d] = a2;
    g_part[blockIdx.y][2][d] = cB;
    g_part[blockIdx.y][3][d] = cBf;
}

__global__ void precompute_reduce_kernel() {
    int d = blockIdx.x * 256 + threadIdx.x;    // 0..1023
#pragma unroll
    for (int v = 0; v < 4; ++v) {
        float s = 0.f;
#pragma unroll
        for (int k = 0; k < 16; ++k) s += g_part[k][v][d];
        g_vecs[v * DD + d] = s;
    }
}

// ---------------------------------------------------------------------------
// K2a: boundary dots — g_bnd[b][0] = u[b,0]·w1, g_bnd[b][1] = u[b,T-1]·w2.
// One block of 512 threads (16 warps, one per (b,kind)).
// ---------------------------------------------------------------------------
__global__ void boundary_kernel(const float* __restrict__ u,
                                const float* __restrict__ w1,
                                const float* __restrict__ w2) {
    int wid  = threadIdx.x >> 5;
    int lane = threadIdx.x & 31;
    int b    = wid >> 1;
    int kind = wid & 1;
    int row  = b * TT + kind * (TT - 1);
    const float* vec = kind ? w2 : w1;
    const float* ur  = u + (size_t)row * DD;
    float s = 0.f;
#pragma unroll
    for (int it = 0; it < 8; ++it) {
        int i = lane * 4 + it * 128;
        float4 uu = *(const float4*)(ur + i);
        float4 vv = *(const float4*)(vec + i);
        s += dot4(uu, vv);
    }
#pragma unroll
    for (int off = 16; off > 0; off >>= 1)
        s += __shfl_down_sync(0xffffffffu, s, off);
    if (lane == 0) g_bnd[b][kind] = s;
}

// ---------------------------------------------------------------------------
// K2b: gamma5 — per-row 5 dots with REGISTER-RESIDENT vectors + fp16 u emit.
// grid 512 blocks x 256 thr; warp w owns d-slice [w*128, w*128+128),
// streams 64 rows. Per row: 1 LDG.128 + 1 STG.64 + 20 FMA + 25 SHFL.
// ---------------------------------------------------------------------------
__global__ __launch_bounds__(256)
void gamma5_kernel(const float* __restrict__ u, const float* __restrict__ Wc) {
    const int wid  = threadIdx.x >> 5;
    const int lane = threadIdx.x & 31;
    const int d    = wid * 128 + lane * 4;
    const int row0 = blockIdx.x * 64;

    const float4 va1 = *(const float4*)(g_vecs + d);
    const float4 va2 = *(const float4*)(g_vecs + DD + d);
    const float4 vcB = *(const float4*)(g_vecs + 2 * DD + d);
    const float4 vcF = *(const float4*)(g_vecs + 3 * DD + d);
    const float4 vwc = *(const float4*)(Wc + d);

#pragma unroll 4
    for (int r = 0; r < 64; ++r) {
        const int row = row0 + r;
        float4 uu = *(const float4*)(u + (size_t)row * DD + d);

        union { __half h[4]; uint2 v; } H;
        H.h[0] = __float2half_rn(uu.x);  H.h[1] = __float2half_rn(uu.y);
        H.h[2] = __float2half_rn(uu.z);  H.h[3] = __float2half_rn(uu.w);
        *(uint2*)(g_Af + (size_t)row * DD + d) = H.v;

        float s0 = dot4(uu, va1);
        float s1 = dot4(uu, va2);
        float s2 = dot4(uu, vcB);
        float s3 = dot4(uu, vcF);
        float s4 = dot4(uu, vwc);
#pragma unroll
        for (int off = 16; off > 0; off >>= 1) {
            s0 += __shfl_down_sync(0xffffffffu, s0, off);
            s1 += __shfl_down_sync(0xffffffffu, s1, off);
            s2 += __shfl_down_sync(0xffffffffu, s2, off);
            s3 += __shfl_down_sync(0xffffffffu, s3, off);
            s4 += __shfl_down_sync(0xffffffffu, s4, off);
        }
        if (lane == 0) {
            g_p5[wid][0][row] = s0;
            g_p5[wid][1][row] = s1;
            g_p5[wid][2][row] = s2;
            g_p5[wid][3][row] = s3;
            g_p5[wid][4][row] = s4;
        }
    }
}

// ---------------------------------------------------------------------------
// K2c: combine partials -> gamma, final. One thread per row.
//   interior: s1=pa1(m), s2=pa2(m+1), cf=pcB(m), cb=pcBf(m+1), cu=pwc(m)
//   t==0:     s1=g_bnd[b][0], cf=pwc(m)
//   t==T-1:   s2=g_bnd[b][1], cb=pwc(m)
// ---------------------------------------------------------------------------
__global__ void gamma_combine_kernel(const float* __restrict__ bias,
                                     float* __restrict__ gamma_out,
                                     float* __restrict__ final_out) {
    int m = blockIdx.x * 256 + threadIdx.x;
    int t = m & (TT - 1);
    int mn = (t == TT - 1) ? m : m + 1;

    float pa1 = 0.f, pa2n = 0.f, pcB = 0.f, pcFn = 0.f, pwc = 0.f;
#pragma unroll
    for (int k = 0; k < 8; ++k) {
        pa1  += g_p5[k][0][m];
        pa2n += g_p5[k][1][mn];
        pcB  += g_p5[k][2][m];
        pcFn += g_p5[k][3][mn];
        pwc  += g_p5[k][4][m];
    }
    int b = m >> 12;                 // m / TT
    float s1 = (t == 0)      ? g_bnd[b][0] : pa1;
    float cf = (t == 0)      ? pwc         : pcB;
    float s2 = (t == TT - 1) ? g_bnd[b][1] : pa2n;
    float cb = (t == TT - 1) ? pwc         : pcFn;
    float cu = pwc;

    float g   = 1.f / (1.f + expf(-(s1 + s2 + bias[0])));
    float fin = 1.f / (1.f + expf(-(g * (cf + cb) + (1.f - g) * cu)));
    g_gamma[m]   = g;
    gamma_out[m] = g;
    final_out[m] = fin;
}

// ---------------------------------------------------------------------------
// K3: fused HMMA GEMM + y epilogue. 256 threads, 2 CTAs/SM, ONE barrier/chunk.
// (identical to R13)  grid (1024/64 = 16, 32768/128 = 256).
// ---------------------------------------------------------------------------
__global__ __launch_bounds__(256, 2)
void gemm_fused_kernel(const float* __restrict__ u, float* __restrict__ y) {
    extern __shared__ __align__(128) char dsm[];
    const uint32_t sbase = smem_u32(dsm);

    const int tid  = threadIdx.x;
    const int wid  = tid >> 5;
    const int lane = tid & 31;
    const int bm = blockIdx.y * BM;
    const int bj = blockIdx.x * XN;     // V column offset (0..960)

    const int grp = wid >> 2;           // 0: C1 (row m), 1: C2 (row m+1)
    const int w2  = wid & 3;
    const int wm  = (w2 >> 1) * 64;     // warp m offset (0/64)
    const int wn  = (w2 & 1) * 32;      // warp n offset within 64 (0/32)

    const int lrow = tid >> 3;          // 0..31 (+j*32)
    const int lchk = tid & 7;
    auto load_stage = [&](int kchunk, int slot) {
        uint32_t sb = sbase + slot * STAGE_BYTES;
        int kb = kchunk * BK;
#pragma unroll
        for (int j = 0; j < 4; ++j) {
            int r = lrow + j * 32;
            uint32_t so = (uint32_t)(r * 128) + (uint32_t)((lchk ^ (r & 7)) << 4);
            int rb = bj + r + ((r >> 6) * (DD - XN));   // rows 0-63: WB, 64-127: WBf
            cpasync16(sb + OFF_A + so, g_Af + (size_t)(bm + r) * KK + kb + lchk * 8);
            cpasync16(sb + OFF_B + so, g_Bf + (size_t)rb * KK + kb + lchk * 8);
        }
        if (tid < 8) {                  // A row 128 (clamped at last CTA)
            int ra = bm + 128;  if (ra > ROWS - 1) ra = ROWS - 1;
            cpasync16(sb + OFF_A + 128 * 128 + tid * 16,
                      g_Af + (size_t)ra * KK + kb + tid * 8);
        }
    };

    uint32_t a_base[4], b_base[2];
    int a_rx[4], b_rx[2];
    const int a_ch = lane >> 4;
    const int b_ch = (lane >> 3) & 1;
#pragma unroll
    for (int mi = 0; mi < 4; ++mi) {
        int r = wm + mi * 16 + (lane & 15) + grp;
        a_base[mi] = OFF_A + (uint32_t)(r * 128);
        a_rx[mi] = r & 7;
    }
#pragma unroll
    for (int p = 0; p < 2; ++p) {
        int r = grp * 64 + wn + p * 16 + (lane & 7) + ((lane >> 4) << 3);
        b_base[p] = OFF_B + (uint32_t)(r * 128);
        b_rx[p] = r & 7;
    }

    float acc[4][4][4];
#pragma unroll
    for (int mi = 0; mi < 4; ++mi)
#pragma unroll
        for (int nj = 0; nj < 4; ++nj)
#pragma unroll
            for (int q = 0; q < 4; ++q) acc[mi][nj][q] = 0.f;

    load_stage(0, 0); CP_COMMIT();
    load_stage(1, 1); CP_COMMIT();

    for (int c = 0; c < NCHUNK; ++c) {
        if (c < NCHUNK - 1) CP_WAIT_1(); else CP_WAIT_0();
        __syncthreads();

        if (c + 2 < NCHUNK) {
            load_stage(c + 2, (c + 2) % STAGES);
            CP_COMMIT();
        }

        const uint32_t slot = sbase + (uint32_t)((c % STAGES) * STAGE_BYTES);

#pragma unroll
        for (int ks = 0; ks < 4; ++ks) {
            const int kc = ks * 2;
            uint32_t af[16], bf[8];
#pragma unroll
            for (int mi = 0; mi < 4; ++mi)
                ldm_x4(af + mi * 4, slot + a_base[mi] + (uint32_t)(((kc + a_ch) ^ a_rx[mi]) << 4));
#pragma unroll
            for (int p = 0; p < 2; ++p)
                ldm_x4(bf + p * 4, slot + b_base[p] + (uint32_t)(((kc + b_ch) ^ b_rx[p]) << 4));
#pragma unroll
            for (int mi = 0; mi < 4; ++mi)
#pragma unroll
                for (int nj = 0; nj < 4; ++nj)
                    mma16816(acc[mi][nj], af + mi * 4, bf + nj * 2);
        }
    }
    __syncthreads();   // everyone done reading SMEM before Cs staging reuses it

    // -- epilogue: stage C1/C2 (fp32) + gamma to smem, then write y --
    float* Cs = (float*)dsm;                       // [2][128][CS_STRIDE]
    float* Gs = Cs + 2 * 128 * CS_STRIDE;          // [128]
    const int lr = lane >> 2;
    const int lc = (lane & 3) * 2;
    float* Cg = Cs + (size_t)grp * 128 * CS_STRIDE;
#pragma unroll
    for (int mi = 0; mi < 4; ++mi) {
#pragma unroll
        for (int nj = 0; nj < 4; ++nj) {
            float* p0 = Cg + (size_t)(wm + mi * 16 + lr) * CS_STRIDE + wn + nj * 8 + lc;
            *(float2*)p0                    = make_float2(acc[mi][nj][0], acc[mi][nj][1]);
            *(float2*)(p0 + 8 * CS_STRIDE)  = make_float2(acc[mi][nj][2], acc[mi][nj][3]);
        }
    }
    if (tid < 128) Gs[tid] = g_gamma[bm + tid];
    __syncthreads();

#pragma unroll
    for (int it = 0; it < 8; ++it) {
        int idx = tid + it * 256;          // 0..2047  (128 rows x 16 col-quads)
        int row = idx >> 4;
        int c4  = (idx & 15) * 4;
        int m = bm + row;
        int t = m & (TT - 1);
        float g  = Gs[row];
        float og = 1.f - g;

        float4 uu = *(const float4*)(u + (size_t)m * DD + bj + c4);
        float4 c1 = *(const float4*)(Cs + (size_t)row * CS_STRIDE + c4);
        float4 c2 = *(const float4*)(Cs + (size_t)(128 + row) * CS_STRIDE + c4);
        float4 xf = (t == 0)      ? uu : c1;
        float4 xb = (t == TT - 1) ? uu : c2;

        float4 out;
        out.x = g * (xf.x + xb.x) + og * uu.x;
        out.y = g * (xf.y + xb.y) + og * uu.y;
        out.z = g * (xf.z + xb.z) + og * uu.z;
        out.w = g * (xf.w + xb.w) + og * uu.w;
        *(float4*)(y + (size_t)m * DD + bj + c4) = out;
    }
}

// ---------------------------------------------------------------------------
// kernel_launch: inputs 0:u 1:WA(dead) 2:WB 3:WAf(dead) 4:WBf 5:w1 6:w2 7:b 8:Wc
// Output: [y | gamma | final] flattened f32.
// ---------------------------------------------------------------------------
extern "C" void kernel_launch(void* const* d_in, const int* in_sizes, int n_in,
                              void* d_out, int out_size) {
    (void)in_sizes; (void)n_in; (void)out_size;
    const float* u   = (const float*)d_in[0];
    const float* WB  = (const float*)d_in[2];
    const float* WBf = (const float*)d_in[4];
    const float* w1  = (const float*)d_in[5];
    const float* w2  = (const float*)d_in[6];
    const float* b   = (const float*)d_in[7];
    const float* Wc  = (const float*)d_in[8];

    float* y         = (float*)d_out;
    float* gamma_out = y + Y_ELEMS;
    float* final_out = gamma_out + G_ELEMS;

    cudaFuncSetAttribute(gemm_fused_kernel,
                         cudaFuncAttributeMaxDynamicSharedMemorySize, SMEM_DYN);

    convert_w_kernel<<<(2 * DD * KK) / 1024, 256>>>(WB, WBf);
    precompute_partial_kernel<<<dim3(DD / 256, 16), 256>>>(WB, WBf, w1, w2, Wc);
    precompute_reduce_kernel<<<DD / 256, 256>>>();
    boundary_kernel<<<1, 512>>>(u, w1, w2);
    gamma5_kernel<<<ROWS / 64, 256>>>(u, Wc);
    gamma_combine_kernel<<<ROWS / 256, 256>>>(b, gamma_out, final_out);
    gemm_fused_kernel<<<dim3(DD / XN, ROWS / BM), 256, SMEM_DYN>>>(u, y);
}